// round 5
// baseline (speedup 1.0000x reference)
#include <cuda_runtime.h>
#include <cuda_fp16.h>
#include <cstdint>

// ---------------- static problem config ----------------
#define T 4096
#define H 1024
#define F 2048
#define E 32
#define KSEL 2
#define CAP 512
#define AUX_COEF 0.01f

// ---------------- device scratch ----------------
__device__ float  g_probs[T * E];
__device__ int    g_top1[T];
__device__ int    g_route_e[T * KSEL];
__device__ float  g_route_w[T * KSEL];
__device__ int    g_route_pos[T * KSEL];
__device__ int    g_route_keep[T * KSEL];
__device__ int    g_count[E];
__device__ __half g_buf[(size_t)E * CAP * H];   // fp16 activations
__device__ float  g_g[(size_t)E * CAP * F];     // raw gate gemm out (f32)
__device__ float  g_u[(size_t)E * CAP * F];     // raw up gemm out (f32)
__device__ float  g_y[(size_t)E * CAP * H];     // expert output

// ---------------- helpers ----------------
__device__ __forceinline__ uint32_t smem_u32(const void* p) {
    uint32_t a;
    asm("{ .reg .u64 t; cvta.to.shared.u64 t, %1; cvt.u32.u64 %0, t; }" : "=r"(a) : "l"(p));
    return a;
}
__device__ __forceinline__ uint32_t packh2(float lo, float hi) {
    __half2 h = __floats2half2_rn(lo, hi);
    return *(uint32_t*)&h;
}
#define STS128(ad, a0, a1, a2, a3) \
    asm volatile("st.shared.v4.b32 [%0], {%1,%2,%3,%4};" :: "r"(ad), "r"(a0), "r"(a1), "r"(a2), "r"(a3) : "memory")
#define LDSM4(r0, r1, r2, r3, ad) \
    asm volatile("ldmatrix.sync.aligned.m8n8.x4.shared.b16 {%0,%1,%2,%3}, [%4];" \
        : "=r"(r0), "=r"(r1), "=r"(r2), "=r"(r3) : "r"(ad))
#define MMA16(d, a, b0v, b1v) \
    asm volatile("mma.sync.aligned.m16n8k16.row.col.f32.f16.f16.f32 " \
        "{%0,%1,%2,%3}, {%4,%5,%6,%7}, {%8,%9}, {%0,%1,%2,%3};" \
        : "+f"(d[0]), "+f"(d[1]), "+f"(d[2]), "+f"(d[3]) \
        : "r"(a[0]), "r"(a[1]), "r"(a[2]), "r"(a[3]), "r"(b0v), "r"(b1v))
#define CP16(dst, src) \
    asm volatile("cp.async.cg.shared.global [%0], [%1], 16;" :: "r"(dst), "l"(src) : "memory")
#define CP_COMMIT() asm volatile("cp.async.commit_group;" ::: "memory")
#define CP_WAIT0()  asm volatile("cp.async.wait_group 0;" ::: "memory")

// ---------------- router ----------------
__global__ void router_kernel(const float* __restrict__ x,
                              const float* __restrict__ Wr,
                              const float* __restrict__ br) {
    int t = blockIdx.x;
    __shared__ float xs[H];
    __shared__ float sl[E];
    int tid = threadIdx.x;
    for (int h = tid; h < H; h += 256) xs[h] = x[(size_t)t * H + h];
    __syncthreads();
    int e = tid >> 3, r = tid & 7;
    float acc = 0.f;
    const float* w = Wr + (size_t)e * H;
    for (int h = r; h < H; h += 8) acc += xs[h] * w[h];
    acc += __shfl_down_sync(0xffffffffu, acc, 4, 8);
    acc += __shfl_down_sync(0xffffffffu, acc, 2, 8);
    acc += __shfl_down_sync(0xffffffffu, acc, 1, 8);
    if (r == 0) sl[e] = acc + br[e];
    __syncthreads();
    if (tid < 32) {
        float l = sl[tid];
        float m = l;
        #pragma unroll
        for (int o = 16; o; o >>= 1) m = fmaxf(m, __shfl_xor_sync(0xffffffffu, m, o));
        float p = __expf(l - m);
        float s = p;
        #pragma unroll
        for (int o = 16; o; o >>= 1) s += __shfl_xor_sync(0xffffffffu, s, o);
        p = p / s;
        g_probs[(size_t)t * E + tid] = p;
        float p1 = p; int i1 = tid;
        #pragma unroll
        for (int o = 16; o; o >>= 1) {
            float op = __shfl_xor_sync(0xffffffffu, p1, o);
            int   oi = __shfl_xor_sync(0xffffffffu, i1, o);
            if (op > p1 || (op == p1 && oi < i1)) { p1 = op; i1 = oi; }
        }
        float pm = (tid == i1) ? -1.f : p;
        float p2 = pm; int i2 = tid;
        #pragma unroll
        for (int o = 16; o; o >>= 1) {
            float op = __shfl_xor_sync(0xffffffffu, p2, o);
            int   oi = __shfl_xor_sync(0xffffffffu, i2, o);
            if (op > p2 || (op == p2 && oi < i2)) { p2 = op; i2 = oi; }
        }
        if (tid == 0) {
            g_top1[t] = i1;
            float mx = fmaxf(p1, p2);
            float e1 = __expf(p1 - mx), e2 = __expf(p2 - mx);
            float inv = 1.f / (e1 + e2);
            g_route_e[2 * t]     = i1; g_route_w[2 * t]     = e1 * inv;
            g_route_e[2 * t + 1] = i2; g_route_w[2 * t + 1] = e2 * inv;
        }
    }
}

// ---------------- dispatch ----------------
__global__ void dispatch_kernel() {
    __shared__ int se[T * KSEL];
    int tid = threadIdx.x;
    for (int i = tid; i < T * KSEL; i += 1024) se[i] = g_route_e[i];
    __syncthreads();
    int warp = tid >> 5, lane = tid & 31;
    int base = 0;
    for (int c = 0; c < T * KSEL; c += 32) {
        int e = se[c + lane];
        unsigned m = __ballot_sync(0xffffffffu, e == warp);
        if (e == warp) {
            int pos = base + __popc(m & ((1u << lane) - 1u));
            g_route_pos[c + lane]  = pos;
            g_route_keep[c + lane] = (pos < CAP) ? 1 : 0;
        }
        base += __popc(m);
    }
    if (lane == 0) g_count[warp] = (base < CAP) ? base : CAP;
}

// ---------------- gather (fp16 conversion) ----------------
__global__ void gather_kernel(const float* __restrict__ x) {
    int i = blockIdx.x;
    if (!g_route_keep[i]) return;
    int t = i >> 1;
    int e = g_route_e[i], pos = g_route_pos[i];
    __half* dst = g_buf + ((size_t)e * CAP + pos) * H;
    const float* src = x + (size_t)t * H;
    int h = threadIdx.x * 4;
    float4 v = *(const float4*)(src + h);
    uint2 o;
    o.x = packh2(v.x, v.y);
    o.y = packh2(v.z, v.w);
    *(uint2*)(dst + h) = o;
}

// ---------------- fp16 mma.sync GEMMs ----------------
// Block 256(M)x128(N), KC=64 halves/stage, 512 thr, 16 warps 4m x 4n (warp 64x32).
// Smem rows: 64 halves = 128B, swizzle chunk16 ^= (row&7)*16.
#define KCH 64
#define AST (256 * 128)   // 256 rows x 128B = 32KB
#define BST (128 * 128)   // 128 rows x 128B = 16KB
#define STG (AST + BST)   // 48KB per stage

// gate/up GEMM: C[m,n] = A @ W, raw f32 out. blockIdx.x<16 -> Wg/g_g else Wu/g_u
__global__ void __launch_bounds__(512, 1) gu_mma(const float* __restrict__ Wg,
                                                 const float* __restrict__ Wu) {
    extern __shared__ char smem[];
    int e = blockIdx.z, cnt = g_count[e];
    int m0 = blockIdx.y * 256;
    if (m0 >= cnt) return;
    int bx = blockIdx.x;
    const float* W = (bx < 16) ? Wg : Wu;
    float* O = ((bx < 16) ? g_g : g_u) + (size_t)e * CAP * F;
    int n0 = (bx & 15) * 128;
    uint32_t sbuf = (smem_u32(smem) + 127u) & ~127u;

    int tid = threadIdx.x, lane = tid & 31, wid = tid >> 5;
    int wm = wid >> 2, wn = wid & 3;

    const __half* A = g_buf + (size_t)e * CAP * H + (size_t)m0 * H;
    const float*  Wb = W + (size_t)e * H * F;

    int ar = tid >> 3, ac = tid & 7;            // A cp.async: row base, chunk
    int bn = tid & 127, kq = tid >> 7;          // B: col n, k-quarter (16 k's)
    uint32_t a_rb = wm * 64 + (lane & 15);
    uint32_t a_sw = (lane & 7) * 16;
    uint32_t a_ch = (lane >> 4) * 16;
    uint32_t b_rb = wn * 32 + (lane & 15);

    float acc[4][4][4] = {};
    uint32_t rbh[8];

    const int NS = H / KCH;   // 16
    // prologue: stage 0
    {
        uint32_t SA = sbuf, SB = SA + AST;
        #pragma unroll
        for (int p = 0; p < 4; p++) {
            int row = ar + p * 64;
            CP16(SA + row * 128 + ((ac * 16) ^ ((row & 7) * 16)),
                 A + (size_t)row * H + ac * 8);
        }
        CP_COMMIT();
        const float* Wp = Wb + (size_t)(kq * 16) * F + n0 + bn;
        #pragma unroll
        for (int q = 0; q < 8; q++)
            rbh[q] = packh2(Wp[(size_t)(2 * q) * F], Wp[(size_t)(2 * q + 1) * F]);
        uint32_t o0 = bn * 128 + (((kq * 2 + 0) * 16) ^ ((bn & 7) * 16));
        uint32_t o1 = bn * 128 + (((kq * 2 + 1) * 16) ^ ((bn & 7) * 16));
        STS128(SB + o0, rbh[0], rbh[1], rbh[2], rbh[3]);
        STS128(SB + o1, rbh[4], rbh[5], rbh[6], rbh[7]);
        CP_WAIT0();
        __syncthreads();
    }

    for (int s = 0; s < NS; s++) {
        if (s + 1 < NS) {
            int k0 = (s + 1) * KCH;
            uint32_t SA = sbuf + ((s + 1) & 1) * STG;
            #pragma unroll
            for (int p = 0; p < 4; p++) {
                int row = ar + p * 64;
                CP16(SA + row * 128 + ((ac * 16) ^ ((row & 7) * 16)),
                     A + (size_t)row * H + k0 + ac * 8);
            }
            CP_COMMIT();
            const float* Wp = Wb + (size_t)(k0 + kq * 16) * F + n0 + bn;
            #pragma unroll
            for (int q = 0; q < 8; q++)
                rbh[q] = packh2(Wp[(size_t)(2 * q) * F], Wp[(size_t)(2 * q + 1) * F]);
        }
        {
            uint32_t SA = sbuf + (s & 1) * STG, SB = SA + AST;
            #pragma unroll
            for (int ks = 0; ks < 4; ks++) {
                uint32_t a[4][4];
                #pragma unroll
                for (int i = 0; i < 4; i++) {
                    uint32_t ad = SA + (a_rb + i * 16) * 128 + ((ks * 32 + a_ch) ^ a_sw);
                    LDSM4(a[i][0], a[i][1], a[i][2], a[i][3], ad);
                }
                uint32_t bq[2][4];
                #pragma unroll
                for (int jj = 0; jj < 2; jj++) {
                    uint32_t bd = SB + (b_rb + jj * 16) * 128 + ((ks * 32 + a_ch) ^ a_sw);
                    LDSM4(bq[jj][0], bq[jj][1], bq[jj][2], bq[jj][3], bd);
                }
                #pragma unroll
                for (int i = 0; i < 4; i++)
                    #pragma unroll
                    for (int j = 0; j < 4; j++)
                        MMA16(acc[i][j], a[i], bq[j >> 1][j & 1], bq[j >> 1][(j & 1) + 2]);
            }
        }
        if (s + 1 < NS) {
            uint32_t SB = sbuf + ((s + 1) & 1) * STG + AST;
            uint32_t o0 = bn * 128 + (((kq * 2 + 0) * 16) ^ ((bn & 7) * 16));
            uint32_t o1 = bn * 128 + (((kq * 2 + 1) * 16) ^ ((bn & 7) * 16));
            STS128(SB + o0, rbh[0], rbh[1], rbh[2], rbh[3]);
            STS128(SB + o1, rbh[4], rbh[5], rbh[6], rbh[7]);
        }
        CP_WAIT0();
        __syncthreads();
    }

    int r0 = m0 + wm * 64 + (lane >> 2);
    int c0 = n0 + wn * 32 + (lane & 3) * 2;
    #pragma unroll
    for (int i = 0; i < 4; i++) {
        #pragma unroll
        for (int j = 0; j < 4; j++) {
            int r = r0 + i * 16, c = c0 + j * 8;
            if (r < cnt)
                *(float2*)(O + (size_t)r * F + c) = make_float2(acc[i][j][0], acc[i][j][1]);
            if (r + 8 < cnt)
                *(float2*)(O + (size_t)(r + 8) * F + c) = make_float2(acc[i][j][2], acc[i][j][3]);
        }
    }
}

// down GEMM: y = (silu(g)*u) @ Wd ; silu fused into A staging
__global__ void __launch_bounds__(512, 1) down_mma(const float* __restrict__ Wd) {
    extern __shared__ char smem[];
    int e = blockIdx.z, cnt = g_count[e];
    int m0 = blockIdx.y * 256;
    if (m0 >= cnt) return;
    int n0 = blockIdx.x * 128;
    uint32_t sbuf = (smem_u32(smem) + 127u) & ~127u;

    int tid = threadIdx.x, lane = tid & 31, wid = tid >> 5;
    int wm = wid >> 2, wn = wid & 3;

    const float* Gb = g_g + ((size_t)e * CAP + m0) * F;
    const float* Ub = g_u + ((size_t)e * CAP + m0) * F;
    const float* Wb = Wd + (size_t)e * F * H;

    int dr = tid >> 1, dh = (tid & 1) * 32;     // A: row, half-offset
    int bn = tid & 127, kq = tid >> 7;
    uint32_t a_rb = wm * 64 + (lane & 15);
    uint32_t a_sw = (lane & 7) * 16;
    uint32_t a_ch = (lane >> 4) * 16;
    uint32_t b_rb = wn * 32 + (lane & 15);

    float acc[4][4][4] = {};
    uint32_t rah[16];
    uint32_t rbh[8];

    const int NS = F / KCH;   // 32
    // prologue stage 0
    {
        uint32_t SA = sbuf, SB = SA + AST;
        const float* Gp = Gb + (size_t)dr * F + dh;
        const float* Up = Ub + (size_t)dr * F + dh;
        #pragma unroll
        for (int q = 0; q < 4; q++) {
            float4 gv0 = *(const float4*)(Gp + q * 8);
            float4 gv1 = *(const float4*)(Gp + q * 8 + 4);
            float4 uv0 = *(const float4*)(Up + q * 8);
            float4 uv1 = *(const float4*)(Up + q * 8 + 4);
            rah[q*4+0] = packh2(gv0.x / (1.f + __expf(-gv0.x)) * uv0.x, gv0.y / (1.f + __expf(-gv0.y)) * uv0.y);
            rah[q*4+1] = packh2(gv0.z / (1.f + __expf(-gv0.z)) * uv0.z, gv0.w / (1.f + __expf(-gv0.w)) * uv0.w);
            rah[q*4+2] = packh2(gv1.x / (1.f + __expf(-gv1.x)) * uv1.x, gv1.y / (1.f + __expf(-gv1.y)) * uv1.y);
            rah[q*4+3] = packh2(gv1.z / (1.f + __expf(-gv1.z)) * uv1.z, gv1.w / (1.f + __expf(-gv1.w)) * uv1.w);
            uint32_t off = dr * 128 + ((((tid & 1) * 4 + q) * 16) ^ ((dr & 7) * 16));
            STS128(SA + off, rah[q*4+0], rah[q*4+1], rah[q*4+2], rah[q*4+3]);
        }
        const float* Wp = Wb + (size_t)(kq * 16) * H + n0 + bn;
        #pragma unroll
        for (int q = 0; q < 8; q++)
            rbh[q] = packh2(Wp[(size_t)(2 * q) * H], Wp[(size_t)(2 * q + 1) * H]);
        uint32_t o0 = bn * 128 + (((kq * 2 + 0) * 16) ^ ((bn & 7) * 16));
        uint32_t o1 = bn * 128 + (((kq * 2 + 1) * 16) ^ ((bn & 7) * 16));
        STS128(SB + o0, rbh[0], rbh[1], rbh[2], rbh[3]);
        STS128(SB + o1, rbh[4], rbh[5], rbh[6], rbh[7]);
        __syncthreads();
    }

    for (int s = 0; s < NS; s++) {
        if (s + 1 < NS) {
            int k0 = (s + 1) * KCH;
            const float* Gp = Gb + (size_t)dr * F + k0 + dh;
            const float* Up = Ub + (size_t)dr * F + k0 + dh;
            #pragma unroll
            for (int q = 0; q < 4; q++) {
                float4 gv0 = *(const float4*)(Gp + q * 8);
                float4 gv1 = *(const float4*)(Gp + q * 8 + 4);
                float4 uv0 = *(const float4*)(Up + q * 8);
                float4 uv1 = *(const float4*)(Up + q * 8 + 4);
                rah[q*4+0] = packh2(gv0.x / (1.f + __expf(-gv0.x)) * uv0.x, gv0.y / (1.f + __expf(-gv0.y)) * uv0.y);
                rah[q*4+1] = packh2(gv0.z / (1.f + __expf(-gv0.z)) * uv0.z, gv0.w / (1.f + __expf(-gv0.w)) * uv0.w);
                rah[q*4+2] = packh2(gv1.x / (1.f + __expf(-gv1.x)) * uv1.x, gv1.y / (1.f + __expf(-gv1.y)) * uv1.y);
                rah[q*4+3] = packh2(gv1.z / (1.f + __expf(-gv1.z)) * uv1.z, gv1.w / (1.f + __expf(-gv1.w)) * uv1.w);
            }
            const float* Wp = Wb + (size_t)(k0 + kq * 16) * H + n0 + bn;
            #pragma unroll
            for (int q = 0; q < 8; q++)
                rbh[q] = packh2(Wp[(size_t)(2 * q) * H], Wp[(size_t)(2 * q + 1) * H]);
        }
        {
            uint32_t SA = sbuf + (s & 1) * STG, SB = SA + AST;
            #pragma unroll
            for (int ks = 0; ks < 4; ks++) {
                uint32_t a[4][4];
                #pragma unroll
                for (int i = 0; i < 4; i++) {
                    uint32_t ad = SA + (a_rb + i * 16) * 128 + ((ks * 32 + a_ch) ^ a_sw);
                    LDSM4(a[i][0], a[i][1], a[i][2], a[i][3], ad);
                }
                uint32_t bq[2][4];
                #pragma unroll
                for (int jj = 0; jj < 2; jj++) {
                    uint32_t bd = SB + (b_rb + jj * 16) * 128 + ((ks * 32 + a_ch) ^ a_sw);
                    LDSM4(bq[jj][0], bq[jj][1], bq[jj][2], bq[jj][3], bd);
                }
                #pragma unroll
                for (int i = 0; i < 4; i++)
                    #pragma unroll
                    for (int j = 0; j < 4; j++)
                        MMA16(acc[i][j], a[i], bq[j >> 1][j & 1], bq[j >> 1][(j & 1) + 2]);
            }
        }
        if (s + 1 < NS) {
            uint32_t SA = sbuf + ((s + 1) & 1) * STG, SB = SA + AST;
            #pragma unroll
            for (int q = 0; q < 4; q++) {
                uint32_t off = dr * 128 + ((((tid & 1) * 4 + q) * 16) ^ ((dr & 7) * 16));
                STS128(SA + off, rah[q*4+0], rah[q*4+1], rah[q*4+2], rah[q*4+3]);
            }
            uint32_t o0 = bn * 128 + (((kq * 2 + 0) * 16) ^ ((bn & 7) * 16));
            uint32_t o1 = bn * 128 + (((kq * 2 + 1) * 16) ^ ((bn & 7) * 16));
            STS128(SB + o0, rbh[0], rbh[1], rbh[2], rbh[3]);
            STS128(SB + o1, rbh[4], rbh[5], rbh[6], rbh[7]);
        }
        __syncthreads();
    }

    float* Y = g_y + (size_t)e * CAP * H;
    int r0 = m0 + wm * 64 + (lane >> 2);
    int c0 = n0 + wn * 32 + (lane & 3) * 2;
    #pragma unroll
    for (int i = 0; i < 4; i++) {
        #pragma unroll
        for (int j = 0; j < 4; j++) {
            int r = r0 + i * 16, c = c0 + j * 8;
            if (r < cnt)
                *(float2*)(Y + (size_t)r * H + c) = make_float2(acc[i][j][0], acc[i][j][1]);
            if (r + 8 < cnt)
                *(float2*)(Y + (size_t)(r + 8) * H + c) = make_float2(acc[i][j][2], acc[i][j][3]);
        }
    }
}

// ---------------- combine ----------------
__global__ void combine_kernel(float* __restrict__ out) {
    int t = blockIdx.x;
    int i0 = 2 * t, i1 = 2 * t + 1;
    int e0 = g_route_e[i0], e1 = g_route_e[i1];
    int k0 = g_route_keep[i0], k1 = g_route_keep[i1];
    int p0 = k0 ? g_route_pos[i0] : 0;
    int p1 = k1 ? g_route_pos[i1] : 0;
    float w0 = k0 ? g_route_w[i0] : 0.f;
    float w1 = k1 ? g_route_w[i1] : 0.f;
    const float* y0 = g_y + ((size_t)e0 * CAP + p0) * H;
    const float* y1 = g_y + ((size_t)e1 * CAP + p1) * H;
    float* o = out + (size_t)t * H;
    int h = threadIdx.x * 4;
    float4 a = *(const float4*)(y0 + h);
    float4 b = *(const float4*)(y1 + h);
    float4 r;
    r.x = w0 * a.x + w1 * b.x;
    r.y = w0 * a.y + w1 * b.y;
    r.z = w0 * a.z + w1 * b.z;
    r.w = w0 * a.w + w1 * b.w;
    *(float4*)(o + h) = r;
}

// ---------------- aux loss ----------------
__global__ void aux_kernel(float* __restrict__ out_aux) {
    int e = threadIdx.x >> 5, lane = threadIdx.x & 31;
    float s = 0.f; int c = 0;
    for (int t = lane; t < T; t += 32) {
        s += g_probs[(size_t)t * E + e];
        c += (g_top1[t] == e) ? 1 : 0;
    }
    #pragma unroll
    for (int o = 16; o; o >>= 1) {
        s += __shfl_xor_sync(0xffffffffu, s, o);
        c += __shfl_xor_sync(0xffffffffu, c, o);
    }
    __shared__ float part[E];
    if (lane == 0) part[e] = (s / (float)T) * ((float)c / (float)T);
    __syncthreads();
    if (threadIdx.x == 0) {
        float a = 0.f;
        for (int i = 0; i < E; i++) a += part[i];
        *out_aux = a * (float)E * AUX_COEF;
    }
}

// ---------------- launch ----------------
extern "C" void kernel_launch(void* const* d_in, const int* in_sizes, int n_in,
                              void* d_out, int out_size) {
    const float* x  = (const float*)d_in[0];
    const float* Wr = (const float*)d_in[1];
    const float* br = (const float*)d_in[2];
    const float* Wg = (const float*)d_in[3];
    const float* Wu = (const float*)d_in[4];
    const float* Wd = (const float*)d_in[5];
    float* out = (float*)d_out;

    int smem = 2 * STG + 128;   // 96KB + pad
    cudaFuncSetAttribute(gu_mma, cudaFuncAttributeMaxDynamicSharedMemorySize, smem);
    cudaFuncSetAttribute(down_mma, cudaFuncAttributeMaxDynamicSharedMemorySize, smem);

    router_kernel<<<T, 256>>>(x, Wr, br);
    dispatch_kernel<<<1, 1024>>>();
    gather_kernel<<<T * KSEL, 256>>>(x);

    dim3 gu_grid(32, CAP / 256, E);          // 16 G n-tiles + 16 U n-tiles
    gu_mma<<<gu_grid, 512, smem>>>(Wg, Wu);

    dim3 dn_grid(H / 128, CAP / 256, E);
    down_mma<<<dn_grid, 512, smem>>>(Wd);

    combine_kernel<<<T, 256>>>(out);

    if (out_size > T * H)
        aux_kernel<<<1, 1024>>>(out + (size_t)T * H);
}

// round 6
// speedup vs baseline: 1.6834x; 1.6834x over previous
#include <cuda_runtime.h>
#include <cuda_fp16.h>
#include <cstdint>

// ---------------- static problem config ----------------
#define T 4096
#define H 1024
#define F 2048
#define E 32
#define KSEL 2
#define CAP 512
#define AUX_COEF 0.01f

// ---------------- device scratch ----------------
__device__ float  g_probs[T * E];
__device__ int    g_top1[T];
__device__ int    g_route_e[T * KSEL];
__device__ float  g_route_w[T * KSEL];
__device__ int    g_route_pos[T * KSEL];
__device__ int    g_route_keep[T * KSEL];
__device__ int    g_count[E];
__device__ __half g_buf[(size_t)E * CAP * H];   // fp16 activations
__device__ __half g_g16[(size_t)E * CAP * F];   // fp16 gate gemm out
__device__ __half g_u16[(size_t)E * CAP * F];   // fp16 up gemm out
__device__ __half g_hid[(size_t)E * CAP * F];   // fp16 silu(g)*u
__device__ float  g_y[(size_t)E * CAP * H];     // expert output

// ---------------- helpers ----------------
__device__ __forceinline__ uint32_t smem_u32(const void* p) {
    uint32_t a;
    asm("{ .reg .u64 t; cvta.to.shared.u64 t, %1; cvt.u32.u64 %0, t; }" : "=r"(a) : "l"(p));
    return a;
}
__device__ __forceinline__ uint32_t packh2(float lo, float hi) {
    __half2 h = __floats2half2_rn(lo, hi);
    return *(uint32_t*)&h;
}
#define STS128(ad, a0, a1, a2, a3) \
    asm volatile("st.shared.v4.b32 [%0], {%1,%2,%3,%4};" :: "r"(ad), "r"(a0), "r"(a1), "r"(a2), "r"(a3) : "memory")
#define LDSM4(r0, r1, r2, r3, ad) \
    asm volatile("ldmatrix.sync.aligned.m8n8.x4.shared.b16 {%0,%1,%2,%3}, [%4];" \
        : "=r"(r0), "=r"(r1), "=r"(r2), "=r"(r3) : "r"(ad))
#define MMA16(d, a, b0v, b1v) \
    asm volatile("mma.sync.aligned.m16n8k16.row.col.f32.f16.f16.f32 " \
        "{%0,%1,%2,%3}, {%4,%5,%6,%7}, {%8,%9}, {%0,%1,%2,%3};" \
        : "+f"(d[0]), "+f"(d[1]), "+f"(d[2]), "+f"(d[3]) \
        : "r"(a[0]), "r"(a[1]), "r"(a[2]), "r"(a[3]), "r"(b0v), "r"(b1v))
#define CP16(dst, src) \
    asm volatile("cp.async.cg.shared.global [%0], [%1], 16;" :: "r"(dst), "l"(src) : "memory")
#define CP_COMMIT() asm volatile("cp.async.commit_group;" ::: "memory")
#define CP_WAIT0()  asm volatile("cp.async.wait_group 0;" ::: "memory")

// ---------------- router ----------------
__global__ void router_kernel(const float* __restrict__ x,
                              const float* __restrict__ Wr,
                              const float* __restrict__ br) {
    int t = blockIdx.x;
    __shared__ float xs[H];
    __shared__ float sl[E];
    int tid = threadIdx.x;
    for (int h = tid; h < H; h += 256) xs[h] = x[(size_t)t * H + h];
    __syncthreads();
    int e = tid >> 3, r = tid & 7;
    float acc = 0.f;
    const float* w = Wr + (size_t)e * H;
    for (int h = r; h < H; h += 8) acc += xs[h] * w[h];
    acc += __shfl_down_sync(0xffffffffu, acc, 4, 8);
    acc += __shfl_down_sync(0xffffffffu, acc, 2, 8);
    acc += __shfl_down_sync(0xffffffffu, acc, 1, 8);
    if (r == 0) sl[e] = acc + br[e];
    __syncthreads();
    if (tid < 32) {
        float l = sl[tid];
        float m = l;
        #pragma unroll
        for (int o = 16; o; o >>= 1) m = fmaxf(m, __shfl_xor_sync(0xffffffffu, m, o));
        float p = __expf(l - m);
        float s = p;
        #pragma unroll
        for (int o = 16; o; o >>= 1) s += __shfl_xor_sync(0xffffffffu, s, o);
        p = p / s;
        g_probs[(size_t)t * E + tid] = p;
        float p1 = p; int i1 = tid;
        #pragma unroll
        for (int o = 16; o; o >>= 1) {
            float op = __shfl_xor_sync(0xffffffffu, p1, o);
            int   oi = __shfl_xor_sync(0xffffffffu, i1, o);
            if (op > p1 || (op == p1 && oi < i1)) { p1 = op; i1 = oi; }
        }
        float pm = (tid == i1) ? -1.f : p;
        float p2 = pm; int i2 = tid;
        #pragma unroll
        for (int o = 16; o; o >>= 1) {
            float op = __shfl_xor_sync(0xffffffffu, p2, o);
            int   oi = __shfl_xor_sync(0xffffffffu, i2, o);
            if (op > p2 || (op == p2 && oi < i2)) { p2 = op; i2 = oi; }
        }
        if (tid == 0) {
            g_top1[t] = i1;
            float mx = fmaxf(p1, p2);
            float e1 = __expf(p1 - mx), e2 = __expf(p2 - mx);
            float inv = 1.f / (e1 + e2);
            g_route_e[2 * t]     = i1; g_route_w[2 * t]     = e1 * inv;
            g_route_e[2 * t + 1] = i2; g_route_w[2 * t + 1] = e2 * inv;
        }
    }
}

// ---------------- dispatch ----------------
__global__ void dispatch_kernel() {
    __shared__ int se[T * KSEL];
    int tid = threadIdx.x;
    for (int i = tid; i < T * KSEL; i += 1024) se[i] = g_route_e[i];
    __syncthreads();
    int warp = tid >> 5, lane = tid & 31;
    int base = 0;
    for (int c = 0; c < T * KSEL; c += 32) {
        int e = se[c + lane];
        unsigned m = __ballot_sync(0xffffffffu, e == warp);
        if (e == warp) {
            int pos = base + __popc(m & ((1u << lane) - 1u));
            g_route_pos[c + lane]  = pos;
            g_route_keep[c + lane] = (pos < CAP) ? 1 : 0;
        }
        base += __popc(m);
    }
    if (lane == 0) g_count[warp] = (base < CAP) ? base : CAP;
}

// ---------------- gather (fp16 conversion) ----------------
__global__ void gather_kernel(const float* __restrict__ x) {
    int i = blockIdx.x;
    if (!g_route_keep[i]) return;
    int t = i >> 1;
    int e = g_route_e[i], pos = g_route_pos[i];
    __half* dst = g_buf + ((size_t)e * CAP + pos) * H;
    const float* src = x + (size_t)t * H;
    int h = threadIdx.x * 4;
    float4 v = *(const float4*)(src + h);
    uint2 o;
    o.x = packh2(v.x, v.y);
    o.y = packh2(v.z, v.w);
    *(uint2*)(dst + h) = o;
}

// ---------------- fp16 mma.sync GEMMs ----------------
// Block 256(M)x128(N), KC=64 halves/stage, 512 thr, 16 warps 4m x 4n (warp 64x32).
// Smem rows: 64 halves = 128B, swizzle chunk16 ^= (row&7)*16.
#define KCH 64
#define AST (256 * 128)   // 32KB
#define BST (128 * 128)   // 16KB
#define STG (AST + BST)   // 48KB per stage

// gate/up GEMM: fp16 out. blockIdx.x<16 -> Wg/g_g16 else Wu/g_u16
__global__ void __launch_bounds__(512, 1) gu_mma(const float* __restrict__ Wg,
                                                 const float* __restrict__ Wu) {
    extern __shared__ char smem[];
    int e = blockIdx.z, cnt = g_count[e];
    int m0 = blockIdx.y * 256;
    if (m0 >= cnt) return;
    int bx = blockIdx.x;
    const float* W = (bx < 16) ? Wg : Wu;
    __half* O = ((bx < 16) ? g_g16 : g_u16) + (size_t)e * CAP * F;
    int n0 = (bx & 15) * 128;
    uint32_t sbuf = (smem_u32(smem) + 127u) & ~127u;

    int tid = threadIdx.x, lane = tid & 31, wid = tid >> 5;
    int wm = wid >> 2, wn = wid & 3;

    const __half* A = g_buf + (size_t)e * CAP * H + (size_t)m0 * H;
    const float*  Wb = W + (size_t)e * H * F;

    int ar = tid >> 3, ac = tid & 7;
    int bn = tid & 127, kq = tid >> 7;
    uint32_t a_rb = wm * 64 + (lane & 15);
    uint32_t a_sw = (lane & 7) * 16;
    uint32_t a_ch = (lane >> 4) * 16;
    uint32_t b_rb = wn * 32 + (lane & 15);

    float acc[4][4][4] = {};
    uint32_t rbh[8];

    const int NS = H / KCH;   // 16
    {
        uint32_t SA = sbuf, SB = SA + AST;
        #pragma unroll
        for (int p = 0; p < 4; p++) {
            int row = ar + p * 64;
            CP16(SA + row * 128 + ((ac * 16) ^ ((row & 7) * 16)),
                 A + (size_t)row * H + ac * 8);
        }
        CP_COMMIT();
        const float* Wp = Wb + (size_t)(kq * 16) * F + n0 + bn;
        #pragma unroll
        for (int q = 0; q < 8; q++)
            rbh[q] = packh2(Wp[(size_t)(2 * q) * F], Wp[(size_t)(2 * q + 1) * F]);
        uint32_t o0 = bn * 128 + (((kq * 2 + 0) * 16) ^ ((bn & 7) * 16));
        uint32_t o1 = bn * 128 + (((kq * 2 + 1) * 16) ^ ((bn & 7) * 16));
        STS128(SB + o0, rbh[0], rbh[1], rbh[2], rbh[3]);
        STS128(SB + o1, rbh[4], rbh[5], rbh[6], rbh[7]);
        CP_WAIT0();
        __syncthreads();
    }

    for (int s = 0; s < NS; s++) {
        if (s + 1 < NS) {
            int k0 = (s + 1) * KCH;
            uint32_t SA = sbuf + ((s + 1) & 1) * STG;
            #pragma unroll
            for (int p = 0; p < 4; p++) {
                int row = ar + p * 64;
                CP16(SA + row * 128 + ((ac * 16) ^ ((row & 7) * 16)),
                     A + (size_t)row * H + k0 + ac * 8);
            }
            CP_COMMIT();
            const float* Wp = Wb + (size_t)(k0 + kq * 16) * F + n0 + bn;
            #pragma unroll
            for (int q = 0; q < 8; q++)
                rbh[q] = packh2(Wp[(size_t)(2 * q) * F], Wp[(size_t)(2 * q + 1) * F]);
        }
        {
            uint32_t SA = sbuf + (s & 1) * STG, SB = SA + AST;
            #pragma unroll
            for (int ks = 0; ks < 4; ks++) {
                uint32_t a[4][4];
                #pragma unroll
                for (int i = 0; i < 4; i++) {
                    uint32_t ad = SA + (a_rb + i * 16) * 128 + ((ks * 32 + a_ch) ^ a_sw);
                    LDSM4(a[i][0], a[i][1], a[i][2], a[i][3], ad);
                }
                uint32_t bq[2][4];
                #pragma unroll
                for (int jj = 0; jj < 2; jj++) {
                    uint32_t bd = SB + (b_rb + jj * 16) * 128 + ((ks * 32 + a_ch) ^ a_sw);
                    LDSM4(bq[jj][0], bq[jj][1], bq[jj][2], bq[jj][3], bd);
                }
                #pragma unroll
                for (int i = 0; i < 4; i++)
                    #pragma unroll
                    for (int j = 0; j < 4; j++)
                        MMA16(acc[i][j], a[i], bq[j >> 1][j & 1], bq[j >> 1][(j & 1) + 2]);
            }
        }
        if (s + 1 < NS) {
            uint32_t SB = sbuf + ((s + 1) & 1) * STG + AST;
            uint32_t o0 = bn * 128 + (((kq * 2 + 0) * 16) ^ ((bn & 7) * 16));
            uint32_t o1 = bn * 128 + (((kq * 2 + 1) * 16) ^ ((bn & 7) * 16));
            STS128(SB + o0, rbh[0], rbh[1], rbh[2], rbh[3]);
            STS128(SB + o1, rbh[4], rbh[5], rbh[6], rbh[7]);
        }
        CP_WAIT0();
        __syncthreads();
    }

    int r0 = m0 + wm * 64 + (lane >> 2);
    int c0 = n0 + wn * 32 + (lane & 3) * 2;
    #pragma unroll
    for (int i = 0; i < 4; i++) {
        #pragma unroll
        for (int j = 0; j < 4; j++) {
            int r = r0 + i * 16, c = c0 + j * 8;
            if (r < cnt)
                *(uint32_t*)(O + (size_t)r * F + c) = packh2(acc[i][j][0], acc[i][j][1]);
            if (r + 8 < cnt)
                *(uint32_t*)(O + (size_t)(r + 8) * F + c) = packh2(acc[i][j][2], acc[i][j][3]);
        }
    }
}

// ---------------- activation: hid = silu(g) * u (fp16 in/out) ----------------
__global__ void act_kernel() {
    size_t i = ((size_t)blockIdx.x * 256 + threadIdx.x) * 8;
    uint4 gv = *(const uint4*)(g_g16 + i);
    uint4 uv = *(const uint4*)(g_u16 + i);
    const uint32_t* gp = (const uint32_t*)&gv;
    const uint32_t* up = (const uint32_t*)&uv;
    uint4 ov;
    uint32_t* op = (uint32_t*)&ov;
    #pragma unroll
    for (int q = 0; q < 4; q++) {
        float2 g2 = __half22float2(*(const __half2*)&gp[q]);
        float2 u2 = __half22float2(*(const __half2*)&up[q]);
        op[q] = packh2(g2.x / (1.f + __expf(-g2.x)) * u2.x,
                       g2.y / (1.f + __expf(-g2.y)) * u2.y);
    }
    *(uint4*)(g_hid + i) = ov;
}

// ---------------- down GEMM: y = hid16 @ Wd ----------------
__global__ void __launch_bounds__(512, 1) down_mma(const float* __restrict__ Wd) {
    extern __shared__ char smem[];
    int e = blockIdx.z, cnt = g_count[e];
    int m0 = blockIdx.y * 256;
    if (m0 >= cnt) return;
    int n0 = blockIdx.x * 128;
    uint32_t sbuf = (smem_u32(smem) + 127u) & ~127u;

    int tid = threadIdx.x, lane = tid & 31, wid = tid >> 5;
    int wm = wid >> 2, wn = wid & 3;

    const __half* A = g_hid + ((size_t)e * CAP + m0) * F;
    const float*  Wb = Wd + (size_t)e * F * H;

    int ar = tid >> 3, ac = tid & 7;
    int bn = tid & 127, kq = tid >> 7;
    uint32_t a_rb = wm * 64 + (lane & 15);
    uint32_t a_sw = (lane & 7) * 16;
    uint32_t a_ch = (lane >> 4) * 16;
    uint32_t b_rb = wn * 32 + (lane & 15);

    float acc[4][4][4] = {};
    uint32_t rbh[8];

    const int NS = F / KCH;   // 32
    {
        uint32_t SA = sbuf, SB = SA + AST;
        #pragma unroll
        for (int p = 0; p < 4; p++) {
            int row = ar + p * 64;
            CP16(SA + row * 128 + ((ac * 16) ^ ((row & 7) * 16)),
                 A + (size_t)row * F + ac * 8);
        }
        CP_COMMIT();
        const float* Wp = Wb + (size_t)(kq * 16) * H + n0 + bn;
        #pragma unroll
        for (int q = 0; q < 8; q++)
            rbh[q] = packh2(Wp[(size_t)(2 * q) * H], Wp[(size_t)(2 * q + 1) * H]);
        uint32_t o0 = bn * 128 + (((kq * 2 + 0) * 16) ^ ((bn & 7) * 16));
        uint32_t o1 = bn * 128 + (((kq * 2 + 1) * 16) ^ ((bn & 7) * 16));
        STS128(SB + o0, rbh[0], rbh[1], rbh[2], rbh[3]);
        STS128(SB + o1, rbh[4], rbh[5], rbh[6], rbh[7]);
        CP_WAIT0();
        __syncthreads();
    }

    for (int s = 0; s < NS; s++) {
        if (s + 1 < NS) {
            int k0 = (s + 1) * KCH;
            uint32_t SA = sbuf + ((s + 1) & 1) * STG;
            #pragma unroll
            for (int p = 0; p < 4; p++) {
                int row = ar + p * 64;
                CP16(SA + row * 128 + ((ac * 16) ^ ((row & 7) * 16)),
                     A + (size_t)row * F + k0 + ac * 8);
            }
            CP_COMMIT();
            const float* Wp = Wb + (size_t)(k0 + kq * 16) * H + n0 + bn;
            #pragma unroll
            for (int q = 0; q < 8; q++)
                rbh[q] = packh2(Wp[(size_t)(2 * q) * H], Wp[(size_t)(2 * q + 1) * H]);
        }
        {
            uint32_t SA = sbuf + (s & 1) * STG, SB = SA + AST;
            #pragma unroll
            for (int ks = 0; ks < 4; ks++) {
                uint32_t a[4][4];
                #pragma unroll
                for (int i = 0; i < 4; i++) {
                    uint32_t ad = SA + (a_rb + i * 16) * 128 + ((ks * 32 + a_ch) ^ a_sw);
                    LDSM4(a[i][0], a[i][1], a[i][2], a[i][3], ad);
                }
                uint32_t bq[2][4];
                #pragma unroll
                for (int jj = 0; jj < 2; jj++) {
                    uint32_t bd = SB + (b_rb + jj * 16) * 128 + ((ks * 32 + a_ch) ^ a_sw);
                    LDSM4(bq[jj][0], bq[jj][1], bq[jj][2], bq[jj][3], bd);
                }
                #pragma unroll
                for (int i = 0; i < 4; i++)
                    #pragma unroll
                    for (int j = 0; j < 4; j++)
                        MMA16(acc[i][j], a[i], bq[j >> 1][j & 1], bq[j >> 1][(j & 1) + 2]);
            }
        }
        if (s + 1 < NS) {
            uint32_t SB = sbuf + ((s + 1) & 1) * STG + AST;
            uint32_t o0 = bn * 128 + (((kq * 2 + 0) * 16) ^ ((bn & 7) * 16));
            uint32_t o1 = bn * 128 + (((kq * 2 + 1) * 16) ^ ((bn & 7) * 16));
            STS128(SB + o0, rbh[0], rbh[1], rbh[2], rbh[3]);
            STS128(SB + o1, rbh[4], rbh[5], rbh[6], rbh[7]);
        }
        CP_WAIT0();
        __syncthreads();
    }

    float* Y = g_y + (size_t)e * CAP * H;
    int r0 = m0 + wm * 64 + (lane >> 2);
    int c0 = n0 + wn * 32 + (lane & 3) * 2;
    #pragma unroll
    for (int i = 0; i < 4; i++) {
        #pragma unroll
        for (int j = 0; j < 4; j++) {
            int r = r0 + i * 16, c = c0 + j * 8;
            if (r < cnt)
                *(float2*)(Y + (size_t)r * H + c) = make_float2(acc[i][j][0], acc[i][j][1]);
            if (r + 8 < cnt)
                *(float2*)(Y + (size_t)(r + 8) * H + c) = make_float2(acc[i][j][2], acc[i][j][3]);
        }
    }
}

// ---------------- combine ----------------
__global__ void combine_kernel(float* __restrict__ out) {
    int t = blockIdx.x;
    int i0 = 2 * t, i1 = 2 * t + 1;
    int e0 = g_route_e[i0], e1 = g_route_e[i1];
    int k0 = g_route_keep[i0], k1 = g_route_keep[i1];
    int p0 = k0 ? g_route_pos[i0] : 0;
    int p1 = k1 ? g_route_pos[i1] : 0;
    float w0 = k0 ? g_route_w[i0] : 0.f;
    float w1 = k1 ? g_route_w[i1] : 0.f;
    const float* y0 = g_y + ((size_t)e0 * CAP + p0) * H;
    const float* y1 = g_y + ((size_t)e1 * CAP + p1) * H;
    float* o = out + (size_t)t * H;
    int h = threadIdx.x * 4;
    float4 a = *(const float4*)(y0 + h);
    float4 b = *(const float4*)(y1 + h);
    float4 r;
    r.x = w0 * a.x + w1 * b.x;
    r.y = w0 * a.y + w1 * b.y;
    r.z = w0 * a.z + w1 * b.z;
    r.w = w0 * a.w + w1 * b.w;
    *(float4*)(o + h) = r;
}

// ---------------- aux loss ----------------
__global__ void aux_kernel(float* __restrict__ out_aux) {
    int e = threadIdx.x >> 5, lane = threadIdx.x & 31;
    float s = 0.f; int c = 0;
    for (int t = lane; t < T; t += 32) {
        s += g_probs[(size_t)t * E + e];
        c += (g_top1[t] == e) ? 1 : 0;
    }
    #pragma unroll
    for (int o = 16; o; o >>= 1) {
        s += __shfl_xor_sync(0xffffffffu, s, o);
        c += __shfl_xor_sync(0xffffffffu, c, o);
    }
    __shared__ float part[E];
    if (lane == 0) part[e] = (s / (float)T) * ((float)c / (float)T);
    __syncthreads();
    if (threadIdx.x == 0) {
        float a = 0.f;
        for (int i = 0; i < E; i++) a += part[i];
        *out_aux = a * (float)E * AUX_COEF;
    }
}

// ---------------- launch ----------------
extern "C" void kernel_launch(void* const* d_in, const int* in_sizes, int n_in,
                              void* d_out, int out_size) {
    const float* x  = (const float*)d_in[0];
    const float* Wr = (const float*)d_in[1];
    const float* br = (const float*)d_in[2];
    const float* Wg = (const float*)d_in[3];
    const float* Wu = (const float*)d_in[4];
    const float* Wd = (const float*)d_in[5];
    float* out = (float*)d_out;

    int smem = 2 * STG + 128;
    cudaFuncSetAttribute(gu_mma, cudaFuncAttributeMaxDynamicSharedMemorySize, smem);
    cudaFuncSetAttribute(down_mma, cudaFuncAttributeMaxDynamicSharedMemorySize, smem);

    router_kernel<<<T, 256>>>(x, Wr, br);
    dispatch_kernel<<<1, 1024>>>();
    gather_kernel<<<T * KSEL, 256>>>(x);

    dim3 gu_grid(32, CAP / 256, E);
    gu_mma<<<gu_grid, 512, smem>>>(Wg, Wu);

    act_kernel<<<(int)(((size_t)E * CAP * F) / 2048), 256>>>();

    dim3 dn_grid(H / 128, CAP / 256, E);
    down_mma<<<dn_grid, 512, smem>>>(Wd);

    combine_kernel<<<T, 256>>>(out);

    if (out_size > T * H)
        aux_kernel<<<1, 1024>>>(out + (size_t)T * H);
}